// round 17
// baseline (speedup 1.0000x reference)
#include <cuda_runtime.h>
#include <cuda_bf16.h>
#include <cstdint>

// ===================== problem constants =====================
static constexpr int GM = 4096, GN = 4096, GK = 4096;

// CTA 128x256, 16 warps as 4(M) x 4(N), warp tile 32x64, K-stage 64.
// 4-stage smem ring, barrier every other iteration (produce 2 tiles ahead).
static constexpr int BM = 128;
static constexpr int BN = 256;
static constexpr int BK = 64;
static constexpr int KTILES = GK / BK;            // 64

static constexpr int A_TILE = BM * BK * 2;        // 16384
static constexpr int B_TILE = BN * BK * 2;        // 32768
static constexpr int STAGE  = A_TILE + B_TILE;    // 49152
static constexpr int SMEM_TOTAL = 4 * STAGE;      // 196608 (<= 227KB cap)

// ===================== PTX helpers =====================
__device__ __forceinline__ uint32_t smem_u32(const void* p) {
    uint32_t a;
    asm("{ .reg .u64 t; cvta.to.shared.u64 t, %1; cvt.u32.u64 %0, t; }" : "=r"(a) : "l"(p));
    return a;
}

#define LDM_X4(r0, r1, r2, r3, addr) \
    asm volatile("ldmatrix.sync.aligned.m8n8.x4.shared.b16 {%0,%1,%2,%3}, [%4];" \
                 : "=r"(r0), "=r"(r1), "=r"(r2), "=r"(r3) : "r"(addr))

#define MMA16816(d0, d1, d2, d3, a0, a1, a2, a3, b0, b1) \
    asm volatile( \
        "mma.sync.aligned.m16n8k16.row.col.f32.bf16.bf16.f32 " \
        "{%0,%1,%2,%3}, {%4,%5,%6,%7}, {%8,%9}, {%0,%1,%2,%3};" \
        : "+f"(d0), "+f"(d1), "+f"(d2), "+f"(d3) \
        : "r"(a0), "r"(a1), "r"(a2), "r"(a3), "r"(b0), "r"(b1))

// Quantize one float4 (quarter of a 16-float BFP group; quad of lanes shares
// the group) and store 8B to swizzled smem.
//  - cross-lane group max: redux.sync.max.u32 over the lane quad (positive
//    floats order as unsigned ints) — replaces 2x shfl + 2x fmax.
//  - round-half-even via magic-add (x*inv exact, power-of-2 scale);
//    upper clamp at +127 (magic+127); -128 unreachable & allowed.
//  - dequant fma-folded: q*scl = fmaf(r, scl, -magic*scl); all products of
//    magic=3*2^22 / integers with scl=2^k are exact, single rounding => exact.
//  - umax(eb, 0x04000000) guards all-zero/denormal groups (q still exact 0).
#define QUNIT(v, saddr) do {                                                   \
        float _m = fmaxf(fmaxf(fabsf((v).x), fabsf((v).y)),                    \
                         fmaxf(fabsf((v).z), fabsf((v).w)));                   \
        uint32_t _mx;                                                          \
        asm("redux.sync.max.u32 %0, %1, %2;"                                   \
            : "=r"(_mx) : "r"(__float_as_uint(_m)), "r"(qrmask));              \
        uint32_t _eb = _mx & 0x7f800000u;                                      \
        _eb = _eb > 0x04000000u ? _eb : 0x04000000u;                           \
        float _inv = __uint_as_float(0x82000000u - _eb);   /* 2^(6-e) */       \
        float _scl = __uint_as_float(_eb - 0x03000000u);   /* 2^(e-6) */       \
        float _nc  = -12582912.f * _scl;                   /* exact */         \
        float _q0 = fmaf(fminf(fmaf((v).x, _inv, 12582912.f), 12583039.f), _scl, _nc); \
        float _q1 = fmaf(fminf(fmaf((v).y, _inv, 12582912.f), 12583039.f), _scl, _nc); \
        float _q2 = fmaf(fminf(fmaf((v).z, _inv, 12582912.f), 12583039.f), _scl, _nc); \
        float _q3 = fmaf(fminf(fmaf((v).w, _inv, 12582912.f), 12583039.f), _scl, _nc); \
        uint32_t _p0, _p1;                                                     \
        asm("cvt.rn.satfinite.bf16x2.f32 %0, %1, %2;" : "=r"(_p0) : "f"(_q1), "f"(_q0)); \
        asm("cvt.rn.satfinite.bf16x2.f32 %0, %1, %2;" : "=r"(_p1) : "f"(_q3), "f"(_q2)); \
        asm volatile("st.shared.v2.b32 [%0], {%1,%2};"                         \
                     :: "r"(saddr), "r"(_p0), "r"(_p1) : "memory");            \
    } while (0)

// ===================== fused BFP GEMM ======================================
__global__ void __launch_bounds__(512, 1)
bfp_gemm_fused(const float* __restrict__ x, const float* __restrict__ w,
               const float* __restrict__ bias, float* __restrict__ out) {
    extern __shared__ char smem[];
    uint32_t sb = smem_u32(smem);
    int tid = threadIdx.x;
    int wid = tid >> 5;
    int lid = tid & 31;
    int wm = wid & 3;        // M warp: 0..3 (32 rows each)
    int wn = wid >> 2;       // N warp: 0..3 (64 cols each)
    int tile_n = blockIdx.x; // 0..15
    int tile_m = blockIdx.y; // 0..31
    uint32_t qrmask = 0xFu << (lid & 28);   // lane-quad mask for redux

    // ---- quant-duty mapping: row tid>>4 (+32i), float4-col tid&15 ----
    int qr = tid >> 4;                // 0..31
    int qc = tid & 15;
    const float4* aP = (const float4*)x + (size_t)(tile_m * BM + qr) * (GK / 4) + qc;
    const float4* bP = (const float4*)w + (size_t)(tile_n * BN + qr) * (GK / 4) + qc;
    const size_t rstep = (size_t)32 * (GK / 4);
    uint32_t sts0 = ((uint32_t)(qr * 128 + qc * 8)) ^ ((uint32_t)(qr & 7) << 4);

    // ---- ldmatrix address components (128B rows, SW128 XOR) ----
    uint32_t a_kx = (uint32_t)((lid >> 4) << 4);
    uint32_t a_off[2], a_mk[2];
#pragma unroll
    for (int am = 0; am < 2; am++) {
        int r = wm * 32 + am * 16 + (lid & 15);
        a_off[am] = (uint32_t)r * 128u;
        a_mk[am]  = (uint32_t)(r & 7) << 4;
    }
    uint32_t b_kx = (uint32_t)(((lid >> 3) & 1) << 4);
    uint32_t b_off[4], b_mk[4];
#pragma unroll
    for (int bn = 0; bn < 4; bn++) {
        int r = wn * 64 + bn * 16 + ((lid >> 4) & 1) * 8 + (lid & 7);
        b_off[bn] = (uint32_t)r * 128u;
        b_mk[bn]  = (uint32_t)(r & 7) << 4;
    }

    float acc[2][8][4];
#pragma unroll
    for (int am = 0; am < 2; am++)
#pragma unroll
        for (int j = 0; j < 8; j++)
#pragma unroll
            for (int c = 0; c < 4; c++) acc[am][j][c] = 0.f;

    // single 4-float4 staging window, reused across three phases per iter
    float4 st[4];

#define LOAD_W(basePtr, kt, ofs) do { _Pragma("unroll") \
        for (int i = 0; i < 4; i++) st[i] = (basePtr)[(size_t)(kt) * 16 + (i + (ofs)) * rstep]; } while (0)
#define Q_W(dstAddr) do { _Pragma("unroll") \
        for (int i = 0; i < 4; i++) QUNIT(st[i], (dstAddr) + (uint32_t)(i * 4096)); } while (0)

#define KS_PHASE(ks) do {                                                      \
            uint32_t ko = (uint32_t)(ks) * 32u;                                \
            uint32_t A[2][4], B[4][4];                                         \
            _Pragma("unroll")                                                  \
            for (int am = 0; am < 2; am++)                                     \
                LDM_X4(A[am][0], A[am][1], A[am][2], A[am][3],                 \
                       cur + a_off[am] + ((ko + a_kx) ^ a_mk[am]));            \
            _Pragma("unroll")                                                  \
            for (int bn = 0; bn < 4; bn++)                                     \
                LDM_X4(B[bn][0], B[bn][1], B[bn][2], B[bn][3],                 \
                       cur + A_TILE + b_off[bn] + ((ko + b_kx) ^ b_mk[bn]));   \
            _Pragma("unroll")                                                  \
            for (int am = 0; am < 2; am++)                                     \
                _Pragma("unroll")                                              \
                for (int j = 0; j < 8; j++)                                    \
                    MMA16816(acc[am][j][0], acc[am][j][1], acc[am][j][2], acc[am][j][3], \
                             A[am][0], A[am][1], A[am][2], A[am][3],           \
                             B[j >> 1][(j & 1) * 2], B[j >> 1][(j & 1) * 2 + 1]); \
        } while (0)

    // ---- prologue: tiles 0 and 1 into buffers 0 and 1 ----
#pragma unroll
    for (int t = 0; t < 2; t++) {
        uint32_t dst = sb + (uint32_t)t * STAGE;
        LOAD_W(aP, t, 0);  Q_W(dst + sts0);
        LOAD_W(bP, t, 0);  Q_W(dst + A_TILE + sts0);
        LOAD_W(bP, t, 4);  Q_W(dst + A_TILE + 16384u + sts0);
    }
    __syncthreads();

    // ---- main loop: produce tile kt+2, consume tile kt, barrier on odd kt --
    for (int kt = 0; kt < KTILES; kt++) {
        uint32_t cur = sb + (uint32_t)(kt & 3) * STAGE;
        uint32_t nx2 = sb + (uint32_t)((kt + 2) & 3) * STAGE;
        bool more = (kt + 2 < KTILES);

        if (more) LOAD_W(aP, kt + 2, 0);          // A window in flight
        KS_PHASE(0);                               // covers A LDG
        if (more) { Q_W(nx2 + sts0); LOAD_W(bP, kt + 2, 0); }
        KS_PHASE(1);                               // covers B0 LDG
        if (more) { Q_W(nx2 + A_TILE + sts0); LOAD_W(bP, kt + 2, 4); }
        KS_PHASE(2);                               // covers B1 LDG
        if (more) Q_W(nx2 + A_TILE + 16384u + sts0);
        KS_PHASE(3);
        if (kt & 1) __syncthreads();               // one barrier per 2 iters
    }
#undef KS_PHASE
#undef LOAD_W
#undef Q_W

    // ---- epilogue ----
#pragma unroll
    for (int am = 0; am < 2; am++) {
        int row0 = tile_m * BM + wm * 32 + am * 16 + (lid >> 2);
#pragma unroll
        for (int j = 0; j < 8; j++) {
            int col = tile_n * BN + wn * 64 + j * 8 + (lid & 3) * 2;
            float2 b2 = *(const float2*)(bias + col);
            float2 v0 = make_float2(acc[am][j][0] + b2.x, acc[am][j][1] + b2.y);
            float2 v1 = make_float2(acc[am][j][2] + b2.x, acc[am][j][3] + b2.y);
            *(float2*)(out + (size_t)row0 * GN + col)       = v0;
            *(float2*)(out + (size_t)(row0 + 8) * GN + col) = v1;
        }
    }
}

// ===================== launch =====================
extern "C" void kernel_launch(void* const* d_in, const int* in_sizes, int n_in,
                              void* d_out, int out_size) {
    const float* x    = (const float*)d_in[0];   // [4096, 4096]
    const float* w    = (const float*)d_in[1];   // [4096, 4096]
    const float* bias = (const float*)d_in[2];   // [4096]
    float* out = (float*)d_out;                  // [4096, 4096]

    (void)in_sizes; (void)n_in; (void)out_size;

    static bool attr_done = false;
    if (!attr_done) {
        cudaFuncSetAttribute(bfp_gemm_fused,
                             cudaFuncAttributeMaxDynamicSharedMemorySize, SMEM_TOTAL);
        attr_done = true;
    }

    dim3 grid(GN / BN, GM / BM);  // (16, 32)
    bfp_gemm_fused<<<grid, 512, SMEM_TOTAL>>>(x, w, bias, out);
}